// round 4
// baseline (speedup 1.0000x reference)
#include <cuda_runtime.h>
#include <cuda_bf16.h>

// ---------------------------------------------------------------------------
// Batched ADMM QP (OSQP-style), N=1024 elements, nx=128, m=192, 100 iters.
// One CTA (256 threads) per batch element; A, Kinv, all vectors SMEM-resident.
// K build + Gauss-Jordan inverse register-resident (64 regs/thread).
// Re-bench attempt 3 (previous two runs died in container infra, not kernel).
// ---------------------------------------------------------------------------

#define NX 128
#define MI 128
#define ME 32
#define MR 160   // stored A rows: ineq (128) + eq (32)
#define MC 192   // total constraints: ineq + eq + (-eq)
#define NITER 100

#define F_ALPHA 1.0f
#define F_EPS   1e-4f
#define F_RHO   0.1f
#define F_SIGMA 1e-6f
#define F_IRHO  10.0f

// smem layout (float offsets)
#define OFF_A    0
#define OFF_K    (OFF_A + MR * NX)        // 20480
#define OFF_TP   (OFF_K + NX * NX)        // 36864 : 8x128 partials / GJ row+col buf
#define OFF_X    (OFF_TP + 8 * NX)        // 37888
#define OFF_Q2   (OFF_X + NX)
#define OFF_RHS  (OFF_Q2 + NX)
#define OFF_Y    (OFF_RHS + NX)
#define OFF_U    (OFF_Y + MC)
#define OFF_VW   (OFF_U + MC)
#define OFF_AXB  (OFF_VW + MR)
#define SMEM_FLOATS (OFF_AXB + MR)        // 38976 floats
#define SMEM_BYTES  (SMEM_FLOATS * 4)     // 155904 B

static_assert(SMEM_BYTES <= 227 * 1024, "smem over sm_100a opt-in limit");

__global__ void __launch_bounds__(256, 1)
admm_qp_kernel(const float* __restrict__ xin,
               const float* __restrict__ Qg,
               const float* __restrict__ qg,
               const float* __restrict__ Ai,
               const float* __restrict__ bi,
               const float* __restrict__ Ae,
               const float* __restrict__ be,
               float* __restrict__ out)
{
    extern __shared__ float sm[];
    const int n   = blockIdx.x;
    const int tid = threadIdx.x;

    float* sA   = sm + OFF_A;    // [160][128] pitch 128
    float* sK   = sm + OFF_K;    // [128][128] Kinv (symmetric)
    float* tp   = sm + OFF_TP;   // [8][128] partials (reused as GJ row+col buf)
    float* sx   = sm + OFF_X;    // [128]
    float* sq2  = sm + OFF_Q2;   // [128] q - alpha*x_in
    float* srhs = sm + OFF_RHS;  // [128]
    float* sy   = sm + OFF_Y;    // [192]
    float* su   = sm + OFF_U;    // [192]
    float* svw  = sm + OFF_VW;   // [160] folded rho*z - y (eq rows combined)
    float* saxb = sm + OFF_AXB;  // [160] A*x for stored rows

    // ---------------- load A (contiguous: smem pitch == gmem row length) ----
    {
        const float4* gi = (const float4*)(Ai + (size_t)n * MI * NX);
        float4* dA = (float4*)sA;
        #pragma unroll 4
        for (int idx = tid; idx < MI * NX / 4; idx += 256) dA[idx] = gi[idx];
        const float4* ge = (const float4*)(Ae + (size_t)n * ME * NX);
        float4* dAe = (float4*)(sA + MI * NX);
        #pragma unroll 2
        for (int idx = tid; idx < ME * NX / 4; idx += 256) dAe[idx] = ge[idx];
    }
    // ---------------- vectors ------------------------------------------------
    if (tid < NX) {
        sq2[tid] = qg[(size_t)n * NX + tid] - F_ALPHA * xin[(size_t)n * NX + tid];
        sx[tid]  = 0.0f;
    }
    if (tid < MC) {
        float u;
        if (tid < MI)            u = bi[(size_t)n * MI + tid];
        else if (tid < MI + ME)  u = be[(size_t)n * ME + (tid - MI)] + F_EPS;
        else                     u = -be[(size_t)n * ME + (tid - MI - ME)];
        su[tid] = u;
        sy[tid] = 0.0f;
    }
    if (tid < MR) svw[tid] = 0.0f;

    // ---------------- K build into registers --------------------------------
    // thread (ri, rh) owns K[ri][64*rh .. 64*rh+63]
    const int ri    = tid >> 1;
    const int rh    = tid & 1;
    const int cbase = rh << 6;

    float M[64];
    {
        const float4* Qrow =
            (const float4*)(Qg + (size_t)n * NX * NX + (size_t)ri * NX + cbase);
        #pragma unroll
        for (int s = 0; s < 16; s++) {
            float4 v = Qrow[s];
            M[4*s+0] = v.x; M[4*s+1] = v.y; M[4*s+2] = v.z; M[4*s+3] = v.w;
        }
    }
    __syncthreads();  // sA + vectors ready

    // K += w_m * A[m][ri] * A[m][cbase+j],  w_m = rho (ineq) / 2*rho (eq)
    for (int m = 0; m < MR; m++) {
        float w = (m < MI) ? F_RHO : (2.0f * F_RHO);
        float t = w * sA[m * NX + ri];
        const float4* arow = (const float4*)(sA + m * NX + cbase);
        #pragma unroll
        for (int s = 0; s < 16; s++) {
            float4 v = arow[s];
            M[4*s+0] = fmaf(t, v.x, M[4*s+0]);
            M[4*s+1] = fmaf(t, v.y, M[4*s+1]);
            M[4*s+2] = fmaf(t, v.z, M[4*s+2]);
            M[4*s+3] = fmaf(t, v.w, M[4*s+3]);
        }
    }
    if (ri >= cbase && ri < cbase + 64)
        M[ri - cbase] += (F_ALPHA + F_SIGMA);   // Qh diag + sigma

    // ---------------- in-place Gauss-Jordan inverse (register resident) -----
    {
        float* rowbuf = tp;          // [128] raw pivot row
        float* colbuf = tp + NX;     // [128] pivot column
        for (int k = 0; k < NX; k++) {
            const int kh = k >> 6;
            const int kj = k & 63;
            __syncthreads();   // prior step's readers done before overwrite
            if (ri == k) {
                #pragma unroll
                for (int s = 0; s < 16; s++)
                    ((float4*)(rowbuf + cbase))[s] =
                        make_float4(M[4*s], M[4*s+1], M[4*s+2], M[4*s+3]);
            }
            if (rh == kh) colbuf[ri] = M[kj];
            __syncthreads();
            const float p = 1.0f / rowbuf[k];
            const float g = colbuf[ri] * p;
            if (ri == k) {
                #pragma unroll
                for (int j = 0; j < 64; j++) M[j] *= p;
                if (rh == kh) M[kj] = p;
            } else {
                #pragma unroll
                for (int s = 0; s < 16; s++) {
                    float4 r4 = ((const float4*)(rowbuf + cbase))[s];
                    M[4*s+0] = fmaf(-g, r4.x, M[4*s+0]);
                    M[4*s+1] = fmaf(-g, r4.y, M[4*s+1]);
                    M[4*s+2] = fmaf(-g, r4.z, M[4*s+2]);
                    M[4*s+3] = fmaf(-g, r4.w, M[4*s+3]);
                }
                if (rh == kh) M[kj] = -g;
            }
        }
    }
    __syncthreads();
    // store Kinv (symmetric): write thread's row as a COLUMN -> conflict-free
    #pragma unroll
    for (int j = 0; j < 64; j++)
        sK[(cbase + j) * NX + ri] = M[j];
    __syncthreads();

    // ---------------- 100 ADMM iterations -----------------------------------
    const int c  = tid & 31;    // lane
    const int hh = tid >> 5;    // warp / group id (0..7)
    const int i0 = c << 2;      // 4-column base

    for (int it = 0; it < NITER; it++) {
        // S1: t = A^T * vw, 8-way row-split partials (column-parallel, float4)
        {
            float ax = 0.f, ay = 0.f, az = 0.f, aw = 0.f;
            const int m0 = hh * 20;
            #pragma unroll
            for (int r = 0; r < 20; r++) {
                const int m = m0 + r;
                const float v = svw[m];
                float4 a4 = *(const float4*)(sA + m * NX + i0);
                ax = fmaf(a4.x, v, ax); ay = fmaf(a4.y, v, ay);
                az = fmaf(a4.z, v, az); aw = fmaf(a4.w, v, aw);
            }
            *(float4*)(tp + hh * NX + i0) = make_float4(ax, ay, az, aw);
        }
        __syncthreads();
        // S2: rhs = sigma*x - q2 + t
        if (tid < NX) {
            float t = 0.f;
            #pragma unroll
            for (int h2 = 0; h2 < 8; h2++) t += tp[h2 * NX + tid];
            srhs[tid] = fmaf(F_SIGMA, sx[tid], t - sq2[tid]);
        }
        __syncthreads();
        // S3: x = Kinv * rhs, 8-way j-split partials (column-parallel, float4)
        {
            float ax = 0.f, ay = 0.f, az = 0.f, aw = 0.f;
            const int j0 = hh * 16;
            #pragma unroll
            for (int r = 0; r < 16; r++) {
                const int j = j0 + r;
                const float v = srhs[j];
                float4 k4 = *(const float4*)(sK + j * NX + i0);
                ax = fmaf(k4.x, v, ax); ay = fmaf(k4.y, v, ay);
                az = fmaf(k4.z, v, az); aw = fmaf(k4.w, v, aw);
            }
            *(float4*)(tp + hh * NX + i0) = make_float4(ax, ay, az, aw);
        }
        __syncthreads();
        // S4: reduce partials -> x
        if (tid < NX) {
            float t = 0.f;
            #pragma unroll
            for (int h2 = 0; h2 < 8; h2++) t += tp[h2 * NX + tid];
            sx[tid] = t;
        }
        __syncthreads();
        // S5: Ax: warp per 20 rows, float4 + butterfly shuffle reduce
        {
            float4 x4 = *(const float4*)(sx + i0);
            const int m0 = hh * 20;
            #pragma unroll
            for (int r = 0; r < 20; r++) {
                const int m = m0 + r;
                float4 a4 = *(const float4*)(sA + m * NX + i0);
                float s = a4.x * x4.x + a4.y * x4.y + a4.z * x4.z + a4.w * x4.w;
                s += __shfl_xor_sync(0xFFFFFFFFu, s, 16);
                s += __shfl_xor_sync(0xFFFFFFFFu, s, 8);
                s += __shfl_xor_sync(0xFFFFFFFFu, s, 4);
                s += __shfl_xor_sync(0xFFFFFFFFu, s, 2);
                s += __shfl_xor_sync(0xFFFFFFFFu, s, 1);
                if (c == 0) saxb[m] = s;
            }
        }
        __syncthreads();
        // S6: z/y updates + fold next-iteration vw = rho*z - y
        if (tid < MI) {
            const float ax = saxb[tid];
            float yv = sy[tid];
            float zv = fminf(fmaf(yv, F_IRHO, ax), su[tid]);
            yv = fmaf(F_RHO, ax - zv, yv);
            sy[tid]  = yv;
            svw[tid] = fmaf(F_RHO, zv, -yv);
        } else if (tid < MR) {
            const int m2 = tid + ME;        // mirrored (-A_eq) row
            const float e = saxb[tid];
            float y1 = sy[tid], y2 = sy[m2];
            float z1 = fminf(fmaf(y1, F_IRHO,  e), su[tid]);
            y1 = fmaf(F_RHO,  e - z1, y1);
            float z2 = fminf(fmaf(y2, F_IRHO, -e), su[m2]);
            y2 = fmaf(F_RHO, -e - z2, y2);
            sy[tid] = y1; sy[m2] = y2;
            svw[tid] = fmaf(F_RHO, z1, -y1) - fmaf(F_RHO, z2, -y2);
        }
        __syncthreads();
    }

    if (tid < NX) out[(size_t)n * NX + tid] = sx[tid];
}

extern "C" void kernel_launch(void* const* d_in, const int* in_sizes, int n_in,
                              void* d_out, int out_size)
{
    const float* xin = (const float*)d_in[0];
    const float* Q   = (const float*)d_in[1];
    const float* q   = (const float*)d_in[2];
    const float* Ai  = (const float*)d_in[3];
    const float* bi  = (const float*)d_in[4];
    const float* Ae  = (const float*)d_in[5];
    const float* be  = (const float*)d_in[6];
    float* out = (float*)d_out;

    const int N = in_sizes[0] / NX;   // 1024

    cudaFuncSetAttribute(admm_qp_kernel,
                         cudaFuncAttributeMaxDynamicSharedMemorySize,
                         SMEM_BYTES);
    admm_qp_kernel<<<N, 256, SMEM_BYTES>>>(xin, Q, q, Ai, bi, Ae, be, out);
}

// round 5
// speedup vs baseline: 1.2253x; 1.2253x over previous
#include <cuda_runtime.h>
#include <cuda_bf16.h>

// ---------------------------------------------------------------------------
// Batched ADMM QP (OSQP-style), N=1024, nx=128, m=192, 100 iters.
// One CTA (256 thr) per element. A tile (80f) and Kinv row (64f) REGISTER-
// resident through the whole iteration loop; smem only for vectors/partials.
// ---------------------------------------------------------------------------

#define NX 128
#define MI 128
#define ME 32
#define MR 160   // stored A rows: ineq(128) + eq(32)
#define MC 192   // constraints: ineq + eq + (-eq)
#define NITER 100

#define F_ALPHA 1.0f
#define F_EPS   1e-4f
#define F_RHO   0.1f
#define F_SIGMA 1e-6f
#define F_IRHO  10.0f

#define TP2_PITCH 33   // conflict-free transpose pitch (pitch%32 == 1)

// smem layout (float offsets)
#define OFF_A    0                       // [160][128]; reused as tp2 in loop
#define OFF_TP   (OFF_A + MR * NX)       // 20480 : 8x128 partials / GJ bufs
#define OFF_X    (OFF_TP + 8 * NX)       // 21504
#define OFF_Q2   (OFF_X + NX)            // 21632
#define OFF_RHS  (OFF_Q2 + NX)           // 21760 (base % 32 == 0)
#define OFF_RHS2 (OFF_RHS + NX + 16)     // 21904 (base % 32 == 16) dup upper half
#define OFF_Y    (OFF_RHS2 + 64)         // 21968
#define OFF_U    (OFF_Y + MC)
#define OFF_VW   (OFF_U + MC)
#define SMEM_FLOATS (OFF_VW + MR)        // 22512 floats
#define SMEM_BYTES  (SMEM_FLOATS * 4)    // 90048 B

static_assert(SMEM_BYTES <= 227 * 1024, "smem over sm_100a opt-in limit");
static_assert((OFF_RHS % 32) == 0, "rhs bank base");
static_assert((OFF_RHS2 % 32) == 16, "rhs2 bank base");

__global__ void __launch_bounds__(256, 1)
admm_qp_kernel(const float* __restrict__ xin,
               const float* __restrict__ Qg,
               const float* __restrict__ qg,
               const float* __restrict__ Ai,
               const float* __restrict__ bi,
               const float* __restrict__ Ae,
               const float* __restrict__ be,
               float* __restrict__ out)
{
    extern __shared__ float sm[];
    const int n   = blockIdx.x;
    const int tid = threadIdx.x;

    float* sA    = sm + OFF_A;    // setup only; becomes tp2 in the loop
    float* tp2   = sm + OFF_A;    // [160][33] Ax partial transpose
    float* tp    = sm + OFF_TP;   // [8][128] S1 partials / GJ row+col bufs
    float* sx    = sm + OFF_X;    // [128]
    float* sq2   = sm + OFF_Q2;   // [128] q - alpha*x_in
    float* srhs  = sm + OFF_RHS;  // [128]
    float* srhs2 = sm + OFF_RHS2; // [64] duplicate of rhs[64..127], +16 banks
    float* sy    = sm + OFF_Y;    // [192]
    float* su    = sm + OFF_U;    // [192]
    float* svw   = sm + OFF_VW;   // [160] folded rho*z - y (eq rows combined)

    // ---------------- load A into smem (contiguous) -------------------------
    {
        const float4* gi = (const float4*)(Ai + (size_t)n * MI * NX);
        float4* dA = (float4*)sA;
        #pragma unroll 4
        for (int idx = tid; idx < MI * NX / 4; idx += 256) dA[idx] = gi[idx];
        const float4* ge = (const float4*)(Ae + (size_t)n * ME * NX);
        float4* dAe = (float4*)(sA + MI * NX);
        #pragma unroll 2
        for (int idx = tid; idx < ME * NX / 4; idx += 256) dAe[idx] = ge[idx];
    }
    // ---------------- vectors ------------------------------------------------
    if (tid < NX) {
        sq2[tid] = qg[(size_t)n * NX + tid] - F_ALPHA * xin[(size_t)n * NX + tid];
        sx[tid]  = 0.0f;
    }
    if (tid < MC) {
        float u;
        if (tid < MI)            u = bi[(size_t)n * MI + tid];
        else if (tid < MI + ME)  u = be[(size_t)n * ME + (tid - MI)] + F_EPS;
        else                     u = -be[(size_t)n * ME + (tid - MI - ME)];
        su[tid] = u;
        sy[tid] = 0.0f;
    }
    if (tid < MR) svw[tid] = 0.0f;

    // ---------------- K build into registers --------------------------------
    // thread (ri, rh) owns K[ri][64*rh .. 64*rh+63]
    const int ri    = tid >> 1;
    const int rh    = tid & 1;
    const int cbase = rh << 6;

    float M[64];
    {
        const float4* Qrow =
            (const float4*)(Qg + (size_t)n * NX * NX + (size_t)ri * NX + cbase);
        #pragma unroll
        for (int s = 0; s < 16; s++) {
            float4 v = Qrow[s];
            M[4*s+0] = v.x; M[4*s+1] = v.y; M[4*s+2] = v.z; M[4*s+3] = v.w;
        }
    }
    __syncthreads();  // sA + vectors ready

    // K += w_m * A[m][ri] * A[m][cbase+j],  w_m = rho (ineq) / 2*rho (eq)
    for (int m = 0; m < MR; m++) {
        float w = (m < MI) ? F_RHO : (2.0f * F_RHO);
        float t = w * sA[m * NX + ri];
        const float4* arow = (const float4*)(sA + m * NX + cbase);
        #pragma unroll
        for (int s = 0; s < 16; s++) {
            float4 v = arow[s];
            M[4*s+0] = fmaf(t, v.x, M[4*s+0]);
            M[4*s+1] = fmaf(t, v.y, M[4*s+1]);
            M[4*s+2] = fmaf(t, v.z, M[4*s+2]);
            M[4*s+3] = fmaf(t, v.w, M[4*s+3]);
        }
    }
    if (ri >= cbase && ri < cbase + 64)
        M[ri - cbase] += (F_ALPHA + F_SIGMA);   // Qh diag + sigma

    // ---------------- in-place Gauss-Jordan inverse (register resident) -----
    {
        float* rowbuf = tp;          // [128] raw pivot row
        float* colbuf = tp + NX;     // [128] pivot column
        for (int k = 0; k < NX; k++) {
            const int kh = k >> 6;
            const int kj = k & 63;
            __syncthreads();   // prior step's readers done before overwrite
            if (ri == k) {
                #pragma unroll
                for (int s = 0; s < 16; s++)
                    ((float4*)(rowbuf + cbase))[s] =
                        make_float4(M[4*s], M[4*s+1], M[4*s+2], M[4*s+3]);
            }
            if (rh == kh) colbuf[ri] = M[kj];
            __syncthreads();
            const float p = 1.0f / rowbuf[k];
            const float g = colbuf[ri] * p;
            if (ri == k) {
                #pragma unroll
                for (int j = 0; j < 64; j++) M[j] *= p;
                if (rh == kh) M[kj] = p;
            } else {
                #pragma unroll
                for (int s = 0; s < 16; s++) {
                    float4 r4 = ((const float4*)(rowbuf + cbase))[s];
                    M[4*s+0] = fmaf(-g, r4.x, M[4*s+0]);
                    M[4*s+1] = fmaf(-g, r4.y, M[4*s+1]);
                    M[4*s+2] = fmaf(-g, r4.z, M[4*s+2]);
                    M[4*s+3] = fmaf(-g, r4.w, M[4*s+3]);
                }
                if (rh == kh) M[kj] = -g;
            }
        }
    }
    __syncthreads();   // GJ done; tp free for S1 partials

    // ---------------- load per-thread A tile into registers -----------------
    const int c  = tid & 31;     // lane
    const int hh = tid >> 5;     // warp id 0..7
    const int i0 = c << 2;       // 4-column base
    const int m0 = hh * 20;      // 20 rows per warp

    float4 Ar[20];
    #pragma unroll
    for (int r = 0; r < 20; r++)
        Ar[r] = *(const float4*)(sA + (m0 + r) * NX + i0);
    // NOTE: tp2 (aliasing sA) is first written in iter-0 S5, which every
    // thread reaches only after 3 CTA-wide barriers following all Ar loads.

    // ---------------- 100 ADMM iterations -----------------------------------
    for (int it = 0; it < NITER; it++) {
        // S1: tp[hh][i] = partial of A^T * vw over this warp's 20 rows (regs)
        {
            float ax = 0.f, ay = 0.f, az = 0.f, aw = 0.f;
            #pragma unroll
            for (int r = 0; r < 20; r++) {
                const float v = svw[m0 + r];      // warp-broadcast LDS
                float4 a4 = Ar[r];
                ax = fmaf(a4.x, v, ax); ay = fmaf(a4.y, v, ay);
                az = fmaf(a4.z, v, az); aw = fmaf(a4.w, v, aw);
            }
            *(float4*)(tp + hh * NX + i0) = make_float4(ax, ay, az, aw);
        }
        __syncthreads();
        // S2: rhs = sigma*x - q2 + reduce(tp); duplicate upper half (+16 banks)
        if (tid < NX) {
            float t = 0.f;
            #pragma unroll
            for (int h2 = 0; h2 < 8; h2++) t += tp[h2 * NX + tid];
            float r = fmaf(F_SIGMA, sx[tid], t - sq2[tid]);
            srhs[tid] = r;
            if (tid >= 64) srhs2[tid - 64] = r;
        }
        __syncthreads();
        // S3: x = Kinv * rhs, Kinv in registers; rhs via 2-bank broadcast LDS
        {
            const float* rsrc = rh ? srhs2 : srhs;
            float p0 = 0.f, p1 = 0.f, p2 = 0.f, p3 = 0.f;
            #pragma unroll
            for (int j = 0; j < 64; j += 4) {
                p0 = fmaf(M[j+0], rsrc[j+0], p0);
                p1 = fmaf(M[j+1], rsrc[j+1], p1);
                p2 = fmaf(M[j+2], rsrc[j+2], p2);
                p3 = fmaf(M[j+3], rsrc[j+3], p3);
            }
            float p = (p0 + p1) + (p2 + p3);
            p += __shfl_xor_sync(0xFFFFFFFFu, p, 1);   // combine rh halves
            if (rh == 0) sx[ri] = p;
        }
        __syncthreads();
        if (it == NITER - 1) break;   // final x is the output; skip dead S5/S6
        // S5: Ax partials -> tp2 transpose (pitch 33, conflict-free)
        {
            float4 x4 = *(const float4*)(sx + i0);
            float* dst = tp2 + m0 * TP2_PITCH + c;
            #pragma unroll
            for (int r = 0; r < 20; r++) {
                float4 a4 = Ar[r];
                float s = fmaf(a4.x, x4.x,
                          fmaf(a4.y, x4.y,
                          fmaf(a4.z, x4.z, a4.w * x4.w)));
                dst[r * TP2_PITCH] = s;
            }
        }
        __syncthreads();
        // S6: reduce Ax row sums + z/y updates + fold vw = rho*z - y
        if (tid < MR) {
            const float* row = tp2 + tid * TP2_PITCH;
            float s0 = 0.f, s1 = 0.f, s2 = 0.f, s3 = 0.f;
            #pragma unroll
            for (int j = 0; j < 32; j += 4) {
                s0 += row[j+0]; s1 += row[j+1];
                s2 += row[j+2]; s3 += row[j+3];
            }
            const float e = (s0 + s1) + (s2 + s3);
            if (tid < MI) {
                float yv = sy[tid];
                float zv = fminf(fmaf(yv, F_IRHO, e), su[tid]);
                yv = fmaf(F_RHO, e - zv, yv);
                sy[tid]  = yv;
                svw[tid] = fmaf(F_RHO, zv, -yv);
            } else {
                const int m2 = tid + ME;        // mirrored (-A_eq) row
                float y1 = sy[tid], y2 = sy[m2];
                float z1 = fminf(fmaf(y1, F_IRHO,  e), su[tid]);
                y1 = fmaf(F_RHO,  e - z1, y1);
                float z2 = fminf(fmaf(y2, F_IRHO, -e), su[m2]);
                y2 = fmaf(F_RHO, -e - z2, y2);
                sy[tid] = y1; sy[m2] = y2;
                svw[tid] = fmaf(F_RHO, z1, -y1) - fmaf(F_RHO, z2, -y2);
            }
        }
        __syncthreads();
    }

    if (tid < NX) out[(size_t)n * NX + tid] = sx[tid];
}

extern "C" void kernel_launch(void* const* d_in, const int* in_sizes, int n_in,
                              void* d_out, int out_size)
{
    const float* xin = (const float*)d_in[0];
    const float* Q   = (const float*)d_in[1];
    const float* q   = (const float*)d_in[2];
    const float* Ai  = (const float*)d_in[3];
    const float* bi  = (const float*)d_in[4];
    const float* Ae  = (const float*)d_in[5];
    const float* be  = (const float*)d_in[6];
    float* out = (float*)d_out;

    const int N = in_sizes[0] / NX;   // 1024

    cudaFuncSetAttribute(admm_qp_kernel,
                         cudaFuncAttributeMaxDynamicSharedMemorySize,
                         SMEM_BYTES);
    admm_qp_kernel<<<N, 256, SMEM_BYTES>>>(xin, Q, q, Ai, bi, Ae, be, out);
}